// round 1
// baseline (speedup 1.0000x reference)
#include <cuda_runtime.h>
#include <cuda_bf16.h>
#include <mma.h>

using namespace nvcuda;

// ---------------- problem constants ----------------
static const int  D_    = 1024;
static const int  HNUM  = 8;
static const int  DK_   = 128;
static const int  NROW  = 16384;       // B*N
static const int  EDIM  = 4096;        // 4*D

// ---------------- device scratch (static; no allocations) ----------------
__device__ __nv_bfloat16 g_xln  [2L*16384*1024];
__device__ __nv_bfloat16 g_wqkv [2L*3*1024*1024];
__device__ __nv_bfloat16 g_wo   [2L*1024*1024];
__device__ __nv_bfloat16 g_w1   [2L*1024*4096];
__device__ __nv_bfloat16 g_w2   [2L*4096*1024];
__device__ __nv_bfloat16 g_qkv  [2L*3*16384*1024];
__device__ float         g_Smat [1024L*256*256];
__device__ __nv_bfloat16 g_Pmat [1024L*256*256];
__device__ __nv_bfloat16 g_Omat [2L*16384*1024];
__device__ float         g_att  [2L*16384*1024];
__device__ __nv_bfloat16 g_attln[2L*16384*1024];
__device__ __nv_bfloat16 g_hid  [2L*16384*4096];

// ---------------- small kernels ----------------
__global__ void cvt_k(const float* __restrict__ s, __nv_bfloat16* __restrict__ d, long n) {
    long i = (long)blockIdx.x * 256 + threadIdx.x;
    if (i < n) d[i] = __float2bfloat16(s[i]);
}

__global__ void ln_k(const float* __restrict__ x, __nv_bfloat16* __restrict__ y,
                     const float* __restrict__ gam, const float* __restrict__ bet) {
    long row = blockIdx.x;
    const float* xr = x + row * 1024;
    int tid = threadIdx.x;
    float v[4]; float s = 0.f, s2 = 0.f;
#pragma unroll
    for (int i = 0; i < 4; i++) { float t = xr[tid + i*256]; v[i] = t; s += t; s2 += t*t; }
#pragma unroll
    for (int o = 16; o; o >>= 1) {
        s  += __shfl_xor_sync(0xffffffffu, s,  o);
        s2 += __shfl_xor_sync(0xffffffffu, s2, o);
    }
    __shared__ float sh[2][8];
    if ((tid & 31) == 0) { sh[0][tid>>5] = s; sh[1][tid>>5] = s2; }
    __syncthreads();
    float S = 0.f, S2 = 0.f;
#pragma unroll
    for (int w = 0; w < 8; w++) { S += sh[0][w]; S2 += sh[1][w]; }
    float m   = S  * (1.f/1024.f);
    float var = S2 * (1.f/1024.f) - m*m;
    float inv = rsqrtf(var + 1e-5f);
#pragma unroll
    for (int i = 0; i < 4; i++) {
        int c = tid + i*256;
        y[row*1024 + c] = __float2bfloat16((v[i]-m)*inv*gam[c] + bet[c]);
    }
}

__global__ void softmax_k(const float* __restrict__ S, __nv_bfloat16* __restrict__ P) {
    long row = (long)blockIdx.x * 8 + (threadIdx.x >> 5);
    int lane = threadIdx.x & 31;
    const float* sr = S + row * 256;
    float v[8]; float m = -1e30f;
#pragma unroll
    for (int e = 0; e < 8; e++) { v[e] = sr[e*32 + lane]; m = fmaxf(m, v[e]); }
#pragma unroll
    for (int o = 16; o; o >>= 1) m = fmaxf(m, __shfl_xor_sync(0xffffffffu, m, o));
    float s = 0.f;
#pragma unroll
    for (int e = 0; e < 8; e++) { v[e] = __expf(v[e] - m); s += v[e]; }
#pragma unroll
    for (int o = 16; o; o >>= 1) s += __shfl_xor_sync(0xffffffffu, s, o);
    float inv = 1.f / s;
#pragma unroll
    for (int e = 0; e < 8; e++)
        P[row*256 + e*32 + lane] = __float2bfloat16(v[e] * inv);
}

// ---------------- GEMM (bf16 in, fp32 acc, wmma/HMMA baseline) ----------------
// EPI: 0 = bf16 store (+opt bias), 1 = fp32 store * alpha,
//      3 = fp32 store: c_res*resid + c_out*(acc+bias), 4 = bf16 gelu(acc+bias)
struct GP {
    const __nv_bfloat16* A;
    const __nv_bfloat16* B;
    long lda, ldb, ldc;
    long sAb, sAh, sBb, sBh, sCb, sCh;
    int  Hh;
    int  K;
    void* C;
    const float* bias;
    const float* resid; long ldr;
    const float* coeffs; int ci0, ci1;
    float alpha;
};

static const int BM = 128, BN = 128, BK = 32;
static const int LDA_S  = BK + 8;   // 40
static const int LDB_NN = BN + 8;   // 136
static const int LDB_NT = BK + 8;   // 40
static const int EPLD   = 20;

template <int EPI, bool TB>
__global__ void __launch_bounds__(256, 2) gemm_k(GP p) {
    __shared__ __align__(16) __nv_bfloat16 As[BM * LDA_S];
    __shared__ __align__(16) __nv_bfloat16 Bs[TB ? BN * LDB_NT : BK * LDB_NN];
    __shared__ float ep[8 * 16 * EPLD];

    const int tid  = threadIdx.x;
    const int warp = tid >> 5, lane = tid & 31;
    const int wm = warp >> 2, wn = warp & 3;   // 2x4 warp grid, 64x32 warp tile

    const int z  = blockIdx.z;
    const int bb = z / p.Hh, hh = z - bb * p.Hh;
    const __nv_bfloat16* Ab = p.A + (long)bb * p.sAb + (long)hh * p.sAh;
    const __nv_bfloat16* Bb = p.B + (long)bb * p.sBb + (long)hh * p.sBh;
    const long coff = (long)bb * p.sCb + (long)hh * p.sCh;

    const int row0 = blockIdx.y * BM;
    const int col0 = blockIdx.x * BN;

    wmma::fragment<wmma::accumulator, 16, 16, 16, float> acc[4][2];
#pragma unroll
    for (int i = 0; i < 4; i++)
#pragma unroll
        for (int j = 0; j < 2; j++) wmma::fill_fragment(acc[i][j], 0.f);

    for (int k0 = 0; k0 < p.K; k0 += BK) {
        // A tile: 128 x 32
#pragma unroll
        for (int it = 0; it < 2; ++it) {
            int idx = (tid + it*256) << 3;
            int r = idx >> 5, c = idx & 31;
            *reinterpret_cast<uint4*>(&As[r*LDA_S + c]) =
                *reinterpret_cast<const uint4*>(Ab + (long)(row0 + r)*p.lda + (k0 + c));
        }
        if (!TB) {  // B tile: 32 x 128 (row major K x N)
#pragma unroll
            for (int it = 0; it < 2; ++it) {
                int idx = (tid + it*256) << 3;
                int r = idx >> 7, c = idx & 127;
                *reinterpret_cast<uint4*>(&Bs[r*LDB_NN + c]) =
                    *reinterpret_cast<const uint4*>(Bb + (long)(k0 + r)*p.ldb + (col0 + c));
            }
        } else {    // B is N x K row major; tile 128(n) x 32(k)
#pragma unroll
            for (int it = 0; it < 2; ++it) {
                int idx = (tid + it*256) << 3;
                int r = idx >> 5, c = idx & 31;
                *reinterpret_cast<uint4*>(&Bs[r*LDB_NT + c]) =
                    *reinterpret_cast<const uint4*>(Bb + (long)(col0 + r)*p.ldb + (k0 + c));
            }
        }
        __syncthreads();

#pragma unroll
        for (int kk = 0; kk < BK; kk += 16) {
            if (!TB) {
                wmma::fragment<wmma::matrix_b, 16, 16, 16, __nv_bfloat16, wmma::row_major> fb[2];
#pragma unroll
                for (int ni = 0; ni < 2; ++ni)
                    wmma::load_matrix_sync(fb[ni], &Bs[kk*LDB_NN + wn*32 + ni*16], LDB_NN);
#pragma unroll
                for (int mi = 0; mi < 4; ++mi) {
                    wmma::fragment<wmma::matrix_a, 16, 16, 16, __nv_bfloat16, wmma::row_major> fa;
                    wmma::load_matrix_sync(fa, &As[(wm*64 + mi*16)*LDA_S + kk], LDA_S);
#pragma unroll
                    for (int ni = 0; ni < 2; ++ni)
                        wmma::mma_sync(acc[mi][ni], fa, fb[ni], acc[mi][ni]);
                }
            } else {
                wmma::fragment<wmma::matrix_b, 16, 16, 16, __nv_bfloat16, wmma::col_major> fb[2];
#pragma unroll
                for (int ni = 0; ni < 2; ++ni)
                    wmma::load_matrix_sync(fb[ni], &Bs[(wn*32 + ni*16)*LDB_NT + kk], LDB_NT);
#pragma unroll
                for (int mi = 0; mi < 4; ++mi) {
                    wmma::fragment<wmma::matrix_a, 16, 16, 16, __nv_bfloat16, wmma::row_major> fa;
                    wmma::load_matrix_sync(fa, &As[(wm*64 + mi*16)*LDA_S + kk], LDA_S);
#pragma unroll
                    for (int ni = 0; ni < 2; ++ni)
                        wmma::mma_sync(acc[mi][ni], fa, fb[ni], acc[mi][ni]);
                }
            }
        }
        __syncthreads();
    }

    // ---------------- epilogue ----------------
    float c_res = 0.f, c_out = 0.f;
    if (EPI == 3) { c_res = p.coeffs[p.ci0]; c_out = p.coeffs[p.ci1]; }
    float* eptr = &ep[warp * 16 * EPLD];
#pragma unroll
    for (int mi = 0; mi < 4; ++mi) {
#pragma unroll
        for (int ni = 0; ni < 2; ++ni) {
            wmma::store_matrix_sync(eptr, acc[mi][ni], EPLD, wmma::mem_row_major);
            __syncwarp();
            int r0 = row0 + wm*64 + mi*16;
            int c0 = col0 + wn*32 + ni*16;
#pragma unroll
            for (int e = 0; e < 8; ++e) {
                int i = e*32 + lane;
                int r = i >> 4, c = i & 15;
                float v = eptr[r*EPLD + c];
                long gr = r0 + r, gc = c0 + c;
                long cidx = coff + gr*p.ldc + gc;
                if (EPI == 0) {
                    if (p.bias) v += p.bias[gc];
                    ((__nv_bfloat16*)p.C)[cidx] = __float2bfloat16(v);
                } else if (EPI == 1) {
                    ((float*)p.C)[cidx] = v * p.alpha;
                } else if (EPI == 3) {
                    v += p.bias[gc];
                    ((float*)p.C)[cidx] = c_res * p.resid[gr*p.ldr + gc] + c_out * v;
                } else if (EPI == 4) {
                    v += p.bias[gc];
                    float gl = 0.5f * v * (1.f + erff(v * 0.70710678118654752f));
                    ((__nv_bfloat16*)p.C)[cidx] = __float2bfloat16(gl);
                }
            }
            __syncwarp();
        }
    }
}

// ---------------- host orchestration ----------------
extern "C" void kernel_launch(void* const* d_in, const int* in_sizes, int n_in,
                              void* d_out, int out_size) {
    (void)in_sizes; (void)n_in; (void)out_size;
    const float* rgb    = (const float*)d_in[0];
    const float* irp    = (const float*)d_in[1];
    const float* ln1g   = (const float*)d_in[2];
    const float* ln1b   = (const float*)d_in[3];
    const float* ln2g   = (const float*)d_in[4];
    const float* ln2b   = (const float*)d_in[5];
    const float* Wqkv_v = (const float*)d_in[6];
    const float* bqkv_v = (const float*)d_in[7];
    const float* Wqkv_i = (const float*)d_in[8];
    const float* bqkv_i = (const float*)d_in[9];
    const float* Wo_v   = (const float*)d_in[10];
    const float* bo_v   = (const float*)d_in[11];
    const float* Wo_i   = (const float*)d_in[12];
    const float* bo_i   = (const float*)d_in[13];
    const float* blng   = (const float*)d_in[14];
    const float* blnb   = (const float*)d_in[15];
    const float* W1_v   = (const float*)d_in[16];
    const float* b1_v   = (const float*)d_in[17];
    const float* W2_v   = (const float*)d_in[18];
    const float* b2_v   = (const float*)d_in[19];
    const float* W1_i   = (const float*)d_in[20];
    const float* b1_i   = (const float*)d_in[21];
    const float* W2_i   = (const float*)d_in[22];
    const float* b2_i   = (const float*)d_in[23];
    const float* coef   = (const float*)d_in[24];
    float* out = (float*)d_out;

    __nv_bfloat16 *xln, *wqkv, *wo, *w1, *w2, *qkv, *Pb, *Ob, *attln, *hb;
    float *Sb, *attb;
    cudaGetSymbolAddress((void**)&xln,   g_xln);
    cudaGetSymbolAddress((void**)&wqkv,  g_wqkv);
    cudaGetSymbolAddress((void**)&wo,    g_wo);
    cudaGetSymbolAddress((void**)&w1,    g_w1);
    cudaGetSymbolAddress((void**)&w2,    g_w2);
    cudaGetSymbolAddress((void**)&qkv,   g_qkv);
    cudaGetSymbolAddress((void**)&Sb,    g_Smat);
    cudaGetSymbolAddress((void**)&Pb,    g_Pmat);
    cudaGetSymbolAddress((void**)&Ob,    g_Omat);
    cudaGetSymbolAddress((void**)&attb,  g_att);
    cudaGetSymbolAddress((void**)&attln, g_attln);
    cudaGetSymbolAddress((void**)&hb,    g_hid);

    // weights -> bf16
    cvt_k<<<12288, 256>>>(Wqkv_v, wqkv,             3145728L);
    cvt_k<<<12288, 256>>>(Wqkv_i, wqkv + 3145728L,  3145728L);
    cvt_k<<<4096,  256>>>(Wo_v,   wo,               1048576L);
    cvt_k<<<4096,  256>>>(Wo_i,   wo + 1048576L,    1048576L);
    cvt_k<<<16384, 256>>>(W1_v,   w1,               4194304L);
    cvt_k<<<16384, 256>>>(W1_i,   w1 + 4194304L,    4194304L);
    cvt_k<<<16384, 256>>>(W2_v,   w2,               4194304L);
    cvt_k<<<16384, 256>>>(W2_i,   w2 + 4194304L,    4194304L);

    // input LayerNorms
    ln_k<<<16384, 256>>>(rgb, xln,             ln1g, ln1b);
    ln_k<<<16384, 256>>>(irp, xln + 16777216L, ln2g, ln2b);

    // QKV projections (6 GEMMs, M=16384 N=1024 K=1024)
    for (int s = 0; s < 2; s++) {
        for (int t = 0; t < 3; t++) {
            GP p{};
            p.A = xln + (long)s * 16777216L;                 p.lda = 1024;
            p.B = wqkv + ((long)s*3 + t) * 1048576L;         p.ldb = 1024;
            p.C = qkv + ((long)s*3 + t) * 16777216L;         p.ldc = 1024;
            p.bias = (s == 0 ? bqkv_v : bqkv_i) + t * 1024;
            p.Hh = 1; p.K = 1024; p.coeffs = coef;
            gemm_k<0, false><<<dim3(8, 128, 1), 256>>>(p);
        }
    }

    // scores S = Q @ K^T * scale  (batched over b,h; dir0: q_ir/k_vis, dir1: q_vis/k_ir)
    for (int dir = 0; dir < 2; ++dir) {
        int qs = (dir == 0) ? 1 : 0;
        int ks = (dir == 0) ? 0 : 1;
        GP p{};
        p.A = qkv + ((long)qs*3 + 0) * 16777216L;  p.lda = 1024; p.sAb = 262144; p.sAh = 128;
        p.B = qkv + ((long)ks*3 + 1) * 16777216L;  p.ldb = 1024; p.sBb = 262144; p.sBh = 128;
        p.C = Sb + (long)dir * 33554432L;          p.ldc = 256;  p.sCb = 524288; p.sCh = 65536;
        p.Hh = 8; p.K = 128; p.alpha = 0.08838834764831845f; p.coeffs = coef;
        gemm_k<1, true><<<dim3(2, 2, 512), 256>>>(p);
    }

    softmax_k<<<32768, 256>>>(Sb, Pb);

    // O = P @ V (batched), written into merged (row, h*128+dk) layout
    for (int dir = 0; dir < 2; ++dir) {
        int ks = (dir == 0) ? 0 : 1;
        GP p{};
        p.A = Pb + (long)dir * 33554432L;          p.lda = 256;  p.sAb = 524288; p.sAh = 65536;
        p.B = qkv + ((long)ks*3 + 2) * 16777216L;  p.ldb = 1024; p.sBb = 262144; p.sBh = 128;
        p.C = Ob + (long)dir * 16777216L;          p.ldc = 1024; p.sCb = 262144; p.sCh = 128;
        p.bias = nullptr; p.Hh = 8; p.K = 256; p.coeffs = coef;
        gemm_k<0, false><<<dim3(1, 2, 512), 256>>>(p);
    }

    // output projection + residual:  att = c_res*input + c_out*(O@Wo + bo)
    for (int dir = 0; dir < 2; ++dir) {
        GP p{};
        p.A = Ob + (long)dir * 16777216L;   p.lda = 1024;
        p.B = wo + (long)dir * 1048576L;    p.ldb = 1024;
        p.C = attb + (long)dir * 16777216L; p.ldc = 1024;
        p.bias = (dir == 0) ? bo_v : bo_i;
        p.resid = (dir == 0) ? rgb : irp;   p.ldr = 1024;
        p.coeffs = coef; p.ci0 = 2*dir; p.ci1 = 2*dir + 1;
        p.Hh = 1; p.K = 1024;
        gemm_k<3, false><<<dim3(8, 128, 1), 256>>>(p);
    }

    // block LayerNorm (shared gamma/beta)
    ln_k<<<16384, 256>>>(attb,             attln,             blng, blnb);
    ln_k<<<16384, 256>>>(attb + 16777216L, attln + 16777216L, blng, blnb);

    // MLP layer 1 with exact GELU epilogue (M=16384 N=4096 K=1024)
    for (int s = 0; s < 2; s++) {
        GP p{};
        p.A = attln + (long)s * 16777216L;  p.lda = 1024;
        p.B = w1 + (long)s * 4194304L;      p.ldb = 4096;
        p.C = hb + (long)s * 67108864L;     p.ldc = 4096;
        p.bias = (s == 0) ? b1_v : b1_i;
        p.Hh = 1; p.K = 1024; p.coeffs = coef;
        gemm_k<4, false><<<dim3(32, 128, 1), 256>>>(p);
    }

    // MLP layer 2 + final combine -> d_out  (M=16384 N=1024 K=4096)
    for (int s = 0; s < 2; s++) {
        GP p{};
        p.A = hb + (long)s * 67108864L;     p.lda = 4096;
        p.B = w2 + (long)s * 4194304L;      p.ldb = 1024;
        p.C = out + (long)s * 16777216L;    p.ldc = 1024;
        p.bias = (s == 0) ? b2_v : b2_i;
        p.resid = attb + (long)s * 16777216L; p.ldr = 1024;
        p.coeffs = coef; p.ci0 = 4 + 2*s; p.ci1 = 5 + 2*s;
        p.Hh = 1; p.K = 4096;
        gemm_k<3, false><<<dim3(8, 128, 1), 256>>>(p);
    }
}

// round 8
// speedup vs baseline: 1.1189x; 1.1189x over previous
#include <cuda_runtime.h>
#include <cuda_bf16.h>
#include <mma.h>
#include <cstdint>

using namespace nvcuda;

// ---------------- device scratch (static; no allocations) ----------------
__device__ __nv_bfloat16 g_xln  [2L*16384*1024];
__device__ __nv_bfloat16 g_wqkv [2L*3*1024*1024];
__device__ __nv_bfloat16 g_wo   [2L*1024*1024];
__device__ __nv_bfloat16 g_w1   [2L*1024*4096];
__device__ __nv_bfloat16 g_w2   [2L*4096*1024];
__device__ __nv_bfloat16 g_qkv  [2L*3*16384*1024];
__device__ float         g_Smat [1024L*256*256];
__device__ __nv_bfloat16 g_Pmat [1024L*256*256];
__device__ __nv_bfloat16 g_Omat [2L*16384*1024];
__device__ float         g_att  [2L*16384*1024];
__device__ __nv_bfloat16 g_attln[2L*16384*1024];
__device__ __nv_bfloat16 g_hid  [2L*16384*4096];

// ---------------- helpers ----------------
__device__ __forceinline__ uint32_t smem_u32(const void* p) {
    uint32_t a;
    asm("{ .reg .u64 t; cvta.to.shared.u64 t, %1; cvt.u32.u64 %0, t; }" : "=r"(a) : "l"(p));
    return a;
}
__device__ __forceinline__ void cpa16(uint32_t d, const void* s) {
    asm volatile("cp.async.cg.shared.global [%0], [%1], 16;" :: "r"(d), "l"(s));
}
#define CP_COMMIT() asm volatile("cp.async.commit_group;" ::: "memory")

// ---------------- small kernels ----------------
__global__ void cvt_k(const float* __restrict__ s, __nv_bfloat16* __restrict__ d, long n) {
    long i = (long)blockIdx.x * 256 + threadIdx.x;
    if (i < n) d[i] = __float2bfloat16(s[i]);
}

__global__ void ln_k(const float* __restrict__ x, __nv_bfloat16* __restrict__ y,
                     const float* __restrict__ gam, const float* __restrict__ bet) {
    long row = blockIdx.x;
    const float* xr = x + row * 1024;
    int tid = threadIdx.x;
    float v[4]; float s = 0.f, s2 = 0.f;
#pragma unroll
    for (int i = 0; i < 4; i++) { float t = xr[tid + i*256]; v[i] = t; s += t; s2 += t*t; }
#pragma unroll
    for (int o = 16; o; o >>= 1) {
        s  += __shfl_xor_sync(0xffffffffu, s,  o);
        s2 += __shfl_xor_sync(0xffffffffu, s2, o);
    }
    __shared__ float sh[2][8];
    if ((tid & 31) == 0) { sh[0][tid>>5] = s; sh[1][tid>>5] = s2; }
    __syncthreads();
    float S = 0.f, S2 = 0.f;
#pragma unroll
    for (int w = 0; w < 8; w++) { S += sh[0][w]; S2 += sh[1][w]; }
    float m   = S  * (1.f/1024.f);
    float var = S2 * (1.f/1024.f) - m*m;
    float inv = rsqrtf(var + 1e-5f);
#pragma unroll
    for (int i = 0; i < 4; i++) {
        int c = tid + i*256;
        y[row*1024 + c] = __float2bfloat16((v[i]-m)*inv*gam[c] + bet[c]);
    }
}

__global__ void softmax_k(const float* __restrict__ S, __nv_bfloat16* __restrict__ P) {
    long row = (long)blockIdx.x * 8 + (threadIdx.x >> 5);
    int lane = threadIdx.x & 31;
    const float* sr = S + row * 256;
    float v[8]; float m = -1e30f;
#pragma unroll
    for (int e = 0; e < 8; e++) { v[e] = sr[e*32 + lane]; m = fmaxf(m, v[e]); }
#pragma unroll
    for (int o = 16; o; o >>= 1) m = fmaxf(m, __shfl_xor_sync(0xffffffffu, m, o));
    float s = 0.f;
#pragma unroll
    for (int e = 0; e < 8; e++) { v[e] = __expf(v[e] - m); s += v[e]; }
#pragma unroll
    for (int o = 16; o; o >>= 1) s += __shfl_xor_sync(0xffffffffu, s, o);
    float inv = 1.f / s;
#pragma unroll
    for (int e = 0; e < 8; e++)
        P[row*256 + e*32 + lane] = __float2bfloat16(v[e] * inv);
}

// ---------------- GEMM params ----------------
struct GP {
    const __nv_bfloat16* A;
    const __nv_bfloat16* B;
    long lda, ldb, ldc;
    long sAb, sAh, sBb, sBh, sCb, sCh;
    int  Hh;
    int  K;
    void* C;
    const float* bias;
    const float* resid; long ldr;
    const float* coeffs; int ci0, ci1;
    float alpha;
};

// ---------------- pipelined wmma GEMM ----------------
// EPI: 0 = bf16 store (+opt bias), 1 = fp32 store * alpha,
//      3 = fp32 store: c_res*resid + c_out*(acc+bias), 4 = bf16 gelu(acc+bias)
static const int BM = 128, BN = 128, BK = 32;
static const int STG = 4;                // cp.async stages
static const int LDA_S  = BK + 8;        // 40 elems = 80 B (16B-multiple)
static const int LDB_NN = BN + 8;        // 136 elems = 272 B (16B-multiple)
static const int LDB_NT = BK + 8;        // 40
static const int EPLD   = 20;
static const int A_STG_B   = BM * LDA_S * 2;      // 10240 B per stage
static const int B_STG_NN  = BK * LDB_NN * 2;     // 8704 B
static const int B_STG_NT  = BN * LDB_NT * 2;     // 10240 B
static const int SMEM_NN   = STG * (A_STG_B + B_STG_NN);  // 75776
static const int SMEM_NT   = STG * (A_STG_B + B_STG_NT);  // 81920

template <int EPI, bool TB>
__global__ void __launch_bounds__(256, 2) gemm_k(GP p) {
    extern __shared__ char dsm[];
    const int tid  = threadIdx.x;
    const int warp = tid >> 5, lane = tid & 31;
    const int wm = warp >> 2, wn = warp & 3;   // 2x4 warp grid, 64x32 warp tile

    const int z  = blockIdx.z;
    const int bb = z / p.Hh, hh = z - bb * p.Hh;
    const __nv_bfloat16* Ab = p.A + (long)bb * p.sAb + (long)hh * p.sAh;
    const __nv_bfloat16* Bb = p.B + (long)bb * p.sBb + (long)hh * p.sBh;
    const long coff = (long)bb * p.sCb + (long)hh * p.sCh;

    const int row0 = blockIdx.y * BM;
    const int col0 = blockIdx.x * BN;
    const long lda = p.lda, ldb = p.ldb;

    const uint32_t asb = smem_u32(dsm);
    const uint32_t bsb = asb + STG * A_STG_B;
    __nv_bfloat16* As = (__nv_bfloat16*)dsm;
    __nv_bfloat16* Bs = (__nv_bfloat16*)(dsm + STG * A_STG_B);

    auto load_stage = [&](int slot, int k0) {
        uint32_t ab = asb + slot * A_STG_B;
#pragma unroll
        for (int it = 0; it < 2; ++it) {
            int id = tid + it*256;
            int r = id >> 2, c = id & 3;
            cpa16(ab + r*80 + c*16, Ab + (long)(row0 + r)*lda + k0 + c*8);
        }
        if (!TB) {
            uint32_t bbp = bsb + slot * B_STG_NN;
#pragma unroll
            for (int it = 0; it < 2; ++it) {
                int id = tid + it*256;
                int r = id >> 4, c = id & 15;
                cpa16(bbp + r*272 + c*16, Bb + (long)(k0 + r)*ldb + col0 + c*8);
            }
        } else {
            uint32_t bbp = bsb + slot * B_STG_NT;
#pragma unroll
            for (int it = 0; it < 2; ++it) {
                int id = tid + it*256;
                int r = id >> 2, c = id & 3;
                cpa16(bbp + r*80 + c*16, Bb + (long)(col0 + r)*ldb + k0 + c*8);
            }
        }
    };

    wmma::fragment<wmma::accumulator, 16, 16, 16, float> acc[4][2];
#pragma unroll
    for (int i = 0; i < 4; i++)
#pragma unroll
        for (int j = 0; j < 2; j++) wmma::fill_fragment(acc[i][j], 0.f);

    const int kiters = p.K >> 5;

    // prologue: issue STG-1 groups
#pragma unroll
    for (int s = 0; s < STG-1; ++s) {
        if (s < kiters) load_stage(s, s * BK);
        CP_COMMIT();
    }

    for (int k = 0; k < kiters; ++k) {
        int pf = k + STG - 1;
        if (pf < kiters) load_stage(pf % STG, pf * BK);
        CP_COMMIT();
        asm volatile("cp.async.wait_group %0;" :: "n"(STG-2));
        __syncthreads();

        int slot = k % STG;
        __nv_bfloat16* Asl = As + slot * (BM * LDA_S);
#pragma unroll
        for (int kk = 0; kk < BK; kk += 16) {
            if (!TB) {
                __nv_bfloat16* Bsl = Bs + slot * (BK * LDB_NN);
                wmma::fragment<wmma::matrix_b, 16, 16, 16, __nv_bfloat16, wmma::row_major> fb[2];
#pragma unroll
                for (int ni = 0; ni < 2; ++ni)
                    wmma::load_matrix_sync(fb[ni], &Bsl[kk*LDB_NN + wn*32 + ni*16], LDB_NN);
#pragma unroll
                for (int mi = 0; mi < 4; ++mi) {
                    wmma::fragment<wmma::matrix_a, 16, 16, 16, __nv_bfloat16, wmma::row_major> fa;
                    wmma::load_matrix_sync(fa, &Asl[(wm*64 + mi*16)*LDA_S + kk], LDA_S);
#pragma unroll
                    for (int ni = 0; ni < 2; ++ni)
                        wmma::mma_sync(acc[mi][ni], fa, fb[ni], acc[mi][ni]);
                }
            } else {
                __nv_bfloat16* Bsl = Bs + slot * (BN * LDB_NT);
                wmma::fragment<wmma::matrix_b, 16, 16, 16, __nv_bfloat16, wmma::col_major> fb[2];
#pragma unroll
                for (int ni = 0; ni < 2; ++ni)
                    wmma::load_matrix_sync(fb[ni], &Bsl[(wn*32 + ni*16)*LDB_NT + kk], LDB_NT);
#pragma unroll
                for (int mi = 0; mi < 4; ++mi) {
                    wmma::fragment<wmma::matrix_a, 16, 16, 16, __nv_bfloat16, wmma::row_major> fa;
                    wmma::load_matrix_sync(fa, &Asl[(wm*64 + mi*16)*LDA_S + kk], LDA_S);
#pragma unroll
                    for (int ni = 0; ni < 2; ++ni)
                        wmma::mma_sync(acc[mi][ni], fa, fb[ni], acc[mi][ni]);
                }
            }
        }
        __syncthreads();
    }

    // ---------------- epilogue (reuse dsm as staging) ----------------
    float c_res = 0.f, c_out = 0.f;
    if (EPI == 3) { c_res = p.coeffs[p.ci0]; c_out = p.coeffs[p.ci1]; }
    float* ep = (float*)dsm;
    float* eptr = &ep[warp * 16 * EPLD];
#pragma unroll
    for (int mi = 0; mi < 4; ++mi) {
#pragma unroll
        for (int ni = 0; ni < 2; ++ni) {
            wmma::store_matrix_sync(eptr, acc[mi][ni], EPLD, wmma::mem_row_major);
            __syncwarp();
            int r0 = row0 + wm*64 + mi*16;
            int c0 = col0 + wn*32 + ni*16;
#pragma unroll
            for (int e = 0; e < 8; ++e) {
                int i = e*32 + lane;
                int r = i >> 4, c = i & 15;
                float v = eptr[r*EPLD + c];
                long gr = r0 + r, gc = c0 + c;
                long cidx = coff + gr*p.ldc + gc;
                if (EPI == 0) {
                    if (p.bias) v += p.bias[gc];
                    ((__nv_bfloat16*)p.C)[cidx] = __float2bfloat16(v);
                } else if (EPI == 1) {
                    ((float*)p.C)[cidx] = v * p.alpha;
                } else if (EPI == 3) {
                    v += p.bias[gc];
                    ((float*)p.C)[cidx] = c_res * p.resid[gr*p.ldr + gc] + c_out * v;
                } else if (EPI == 4) {
                    v += p.bias[gc];
                    float gl = 0.5f * v * (1.f + erff(v * 0.70710678118654752f));
                    ((__nv_bfloat16*)p.C)[cidx] = __float2bfloat16(gl);
                }
            }
            __syncwarp();
        }
    }
}

// ---------------- host orchestration ----------------
extern "C" void kernel_launch(void* const* d_in, const int* in_sizes, int n_in,
                              void* d_out, int out_size) {
    (void)in_sizes; (void)n_in; (void)out_size;
    const float* rgb    = (const float*)d_in[0];
    const float* irp    = (const float*)d_in[1];
    const float* ln1g   = (const float*)d_in[2];
    const float* ln1b   = (const float*)d_in[3];
    const float* ln2g   = (const float*)d_in[4];
    const float* ln2b   = (const float*)d_in[5];
    const float* Wqkv_v = (const float*)d_in[6];
    const float* bqkv_v = (const float*)d_in[7];
    const float* Wqkv_i = (const float*)d_in[8];
    const float* bqkv_i = (const float*)d_in[9];
    const float* Wo_v   = (const float*)d_in[10];
    const float* bo_v   = (const float*)d_in[11];
    const float* Wo_i   = (const float*)d_in[12];
    const float* bo_i   = (const float*)d_in[13];
    const float* blng   = (const float*)d_in[14];
    const float* blnb   = (const float*)d_in[15];
    const float* W1_v   = (const float*)d_in[16];
    const float* b1_v   = (const float*)d_in[17];
    const float* W2_v   = (const float*)d_in[18];
    const float* b2_v   = (const float*)d_in[19];
    const float* W1_i   = (const float*)d_in[20];
    const float* b1_i   = (const float*)d_in[21];
    const float* W2_i   = (const float*)d_in[22];
    const float* b2_i   = (const float*)d_in[23];
    const float* coef   = (const float*)d_in[24];
    float* out = (float*)d_out;

    __nv_bfloat16 *xln, *wqkv, *wo, *w1, *w2, *qkv, *Pb, *Ob, *attln, *hb;
    float *Sb, *attb;
    cudaGetSymbolAddress((void**)&xln,   g_xln);
    cudaGetSymbolAddress((void**)&wqkv,  g_wqkv);
    cudaGetSymbolAddress((void**)&wo,    g_wo);
    cudaGetSymbolAddress((void**)&w1,    g_w1);
    cudaGetSymbolAddress((void**)&w2,    g_w2);
    cudaGetSymbolAddress((void**)&qkv,   g_qkv);
    cudaGetSymbolAddress((void**)&Sb,    g_Smat);
    cudaGetSymbolAddress((void**)&Pb,    g_Pmat);
    cudaGetSymbolAddress((void**)&Ob,    g_Omat);
    cudaGetSymbolAddress((void**)&attb,  g_att);
    cudaGetSymbolAddress((void**)&attln, g_attln);
    cudaGetSymbolAddress((void**)&hb,    g_hid);

    cudaFuncSetAttribute(gemm_k<0, false>, cudaFuncAttributeMaxDynamicSharedMemorySize, SMEM_NN);
    cudaFuncSetAttribute(gemm_k<3, false>, cudaFuncAttributeMaxDynamicSharedMemorySize, SMEM_NN);
    cudaFuncSetAttribute(gemm_k<4, false>, cudaFuncAttributeMaxDynamicSharedMemorySize, SMEM_NN);
    cudaFuncSetAttribute(gemm_k<1, true>,  cudaFuncAttributeMaxDynamicSharedMemorySize, SMEM_NT);

    // weights -> bf16
    cvt_k<<<12288, 256>>>(Wqkv_v, wqkv,             3145728L);
    cvt_k<<<12288, 256>>>(Wqkv_i, wqkv + 3145728L,  3145728L);
    cvt_k<<<4096,  256>>>(Wo_v,   wo,               1048576L);
    cvt_k<<<4096,  256>>>(Wo_i,   wo + 1048576L,    1048576L);
    cvt_k<<<16384, 256>>>(W1_v,   w1,               4194304L);
    cvt_k<<<16384, 256>>>(W1_i,   w1 + 4194304L,    4194304L);
    cvt_k<<<16384, 256>>>(W2_v,   w2,               4194304L);
    cvt_k<<<16384, 256>>>(W2_i,   w2 + 4194304L,    4194304L);

    // input LayerNorms
    ln_k<<<16384, 256>>>(rgb, xln,             ln1g, ln1b);
    ln_k<<<16384, 256>>>(irp, xln + 16777216L, ln2g, ln2b);

    // QKV projections (6 GEMMs, M=16384 N=1024 K=1024)
    for (int s = 0; s < 2; s++) {
        for (int t = 0; t < 3; t++) {
            GP p{};
            p.A = xln + (long)s * 16777216L;                 p.lda = 1024;
            p.B = wqkv + ((long)s*3 + t) * 1048576L;         p.ldb = 1024;
            p.C = qkv + ((long)s*3 + t) * 16777216L;         p.ldc = 1024;
            p.bias = (s == 0 ? bqkv_v : bqkv_i) + t * 1024;
            p.Hh = 1; p.K = 1024; p.coeffs = coef;
            gemm_k<0, false><<<dim3(8, 128, 1), 256, SMEM_NN>>>(p);
        }
    }

    // scores S = Q @ K^T * scale  (batched over b,h)
    for (int dir = 0; dir < 2; ++dir) {
        int qs = (dir == 0) ? 1 : 0;
        int ks = (dir == 0) ? 0 : 1;
        GP p{};
        p.A = qkv + ((long)qs*3 + 0) * 16777216L;  p.lda = 1024; p.sAb = 262144; p.sAh = 128;
        p.B = qkv + ((long)ks*3 + 1) * 16777216L;  p.ldb = 1024; p.sBb = 262144; p.sBh = 128;
        p.C = Sb + (long)dir * 33554432L;          p.ldc = 256;  p.sCb = 524288; p.sCh = 65536;
        p.Hh = 8; p.K = 128; p.alpha = 0.08838834764831845f; p.coeffs = coef;
        gemm_k<1, true><<<dim3(2, 2, 512), 256, SMEM_NT>>>(p);
    }

    softmax_k<<<32768, 256>>>(Sb, Pb);

    // O = P @ V (batched), merged layout
    for (int dir = 0; dir < 2; ++dir) {
        int ks = (dir == 0) ? 0 : 1;
        GP p{};
        p.A = Pb + (long)dir * 33554432L;          p.lda = 256;  p.sAb = 524288; p.sAh = 65536;
        p.B = qkv + ((long)ks*3 + 2) * 16777216L;  p.ldb = 1024; p.sBb = 262144; p.sBh = 128;
        p.C = Ob + (long)dir * 16777216L;          p.ldc = 1024; p.sCb = 262144; p.sCh = 128;
        p.bias = nullptr; p.Hh = 8; p.K = 256; p.coeffs = coef;
        gemm_k<0, false><<<dim3(1, 2, 512), 256, SMEM_NN>>>(p);
    }

    // output projection + residual
    for (int dir = 0; dir < 2; ++dir) {
        GP p{};
        p.A = Ob + (long)dir * 16777216L;   p.lda = 1024;
        p.B = wo + (long)dir * 1048576L;    p.ldb = 1024;
        p.C = attb + (long)dir * 16777216L; p.ldc = 1024;
        p.bias = (dir == 0) ? bo_v : bo_i;
        p.resid = (dir == 0) ? rgb : irp;   p.ldr = 1024;
        p.coeffs = coef; p.ci0 = 2*dir; p.ci1 = 2*dir + 1;
        p.Hh = 1; p.K = 1024;
        gemm_k<3, false><<<dim3(8, 128, 1), 256, SMEM_NN>>>(p);
    }

    // block LayerNorm (shared gamma/beta)
    ln_k<<<16384, 256>>>(attb,             attln,             blng, blnb);
    ln_k<<<16384, 256>>>(attb + 16777216L, attln + 16777216L, blng, blnb);

    // MLP layer 1 + exact GELU (M=16384 N=4096 K=1024)
    for (int s = 0; s < 2; s++) {
        GP p{};
        p.A = attln + (long)s * 16777216L;  p.lda = 1024;
        p.B = w1 + (long)s * 4194304L;      p.ldb = 4096;
        p.C = hb + (long)s * 67108864L;     p.ldc = 4096;
        p.bias = (s == 0) ? b1_v : b1_i;
        p.Hh = 1; p.K = 1024; p.coeffs = coef;
        gemm_k<4, false><<<dim3(32, 128, 1), 256, SMEM_NN>>>(p);
    }

    // MLP layer 2 + final combine -> d_out (M=16384 N=1024 K=4096)
    for (int s = 0; s < 2; s++) {
        GP p{};
        p.A = hb + (long)s * 67108864L;     p.lda = 4096;
        p.B = w2 + (long)s * 4194304L;      p.ldb = 1024;
        p.C = out + (long)s * 16777216L;    p.ldc = 1024;
        p.bias = (s == 0) ? b2_v : b2_i;
        p.resid = attb + (long)s * 16777216L; p.ldr = 1024;
        p.coeffs = coef; p.ci0 = 4 + 2*s; p.ci1 = 5 + 2*s;
        p.Hh = 1; p.K = 4096;
        gemm_k<3, false><<<dim3(8, 128, 1), 256, SMEM_NN>>>(p);
    }
}